// round 13
// baseline (speedup 1.0000x reference)
#include <cuda_runtime.h>
#include <cuda_fp16.h>

typedef unsigned int u32;
typedef unsigned long long u64;

#define B_   64
#define NGF  256
#define S_   2048
#define ENCH 512
#define ZD   64
#define DECH 256
#define TS   128
#define NTILES 16

// ---- smem byte offsets ----
#define U_HI   0         // [256 g][128 s] fp16  64KB
#define A1_HI  65536     // [64 h][256 g] fp16   32KB
#define W2_HI  65536     // overlay on A1 (after GEMM1 done): [64 z][64 h] 8KB
#define HT_HI  98304     // [64 h][128 s] fp16   16KB  (reused by inline decoder)
#define RED_O  114688    // 256 floats
#define SMEM_SZ 115712

__device__ float g_w[B_*NGF];
__device__ float g_c[B_*ENCH];
__device__ float g_zpart[B_*NTILES*ZD];
__device__ __half g_w1t[ENCH*NGF];   // [h][g] = fp16(W1[g][h])
__device__ __half g_w2t[ZD*ENCH];    // [z][h] = fp16(W2[h][z])
__device__ int g_cnt_prep[B_];       // zero-init; self-resetting
__device__ int g_cnt_main[B_];       // zero-init; self-resetting

// ---- helpers ---------------------------------------------------------------
__device__ __forceinline__ u32 smem_u32(const void* p) {
    u32 a;
    asm("{ .reg .u64 t; cvta.to.shared.u64 t, %1; cvt.u32.u64 %0, t; }"
        : "=r"(a) : "l"(p));
    return a;
}
__device__ __forceinline__ void ldsm4(u32* r, u32 addr) {
    asm volatile("ldmatrix.sync.aligned.m8n8.x4.shared.b16 {%0,%1,%2,%3}, [%4];"
        : "=r"(r[0]), "=r"(r[1]), "=r"(r[2]), "=r"(r[3]) : "r"(addr));
}
__device__ __forceinline__ void ldsm4t(u32* r, u32 addr) {
    asm volatile("ldmatrix.sync.aligned.m8n8.x4.trans.shared.b16 {%0,%1,%2,%3}, [%4];"
        : "=r"(r[0]), "=r"(r[1]), "=r"(r[2]), "=r"(r[3]) : "r"(addr));
}
__device__ __forceinline__ void mma_h(float* c, const u32* a, u32 b0, u32 b1) {
    asm volatile("mma.sync.aligned.m16n8k16.row.col.f32.f16.f16.f32 "
        "{%0,%1,%2,%3}, {%4,%5,%6,%7}, {%8,%9}, {%0,%1,%2,%3};"
        : "+f"(c[0]), "+f"(c[1]), "+f"(c[2]), "+f"(c[3])
        : "r"(a[0]), "r"(a[1]), "r"(a[2]), "r"(a[3]), "r"(b0), "r"(b1));
}
__device__ __forceinline__ u32 packh2(float lo, float hi) {
    __half2 h = __floats2half2_rn(lo, hi);
    return *(u32*)&h;
}

// ---------------------------------------------------------------------------
// Fused prep kernel: grid sections.
//   blocks [0, 2048)    : rowsum (one warp per (b,g) row); last block per batch
//                         (32 blocks/batch) computes cvec + len==0 output.
//   blocks [2048, 2560) : prep_w1t
//   blocks [2560, 2688) : prep_w2t
// ---------------------------------------------------------------------------
__global__ void __launch_bounds__(256)
prep_all_kernel(const float* __restrict__ u, const int* __restrict__ lengths,
                const float* __restrict__ W1, const float* __restrict__ W2,
                const float* __restrict__ b1, const float* __restrict__ b3,
                const float* __restrict__ W4, const float* __restrict__ b4,
                float* __restrict__ y) {
    int bid = blockIdx.x;
    int tid = threadIdx.x;
    if (bid < 2048) {
        int warp = (bid * 256 + tid) >> 5;            // 0 .. 16383
        int lane = tid & 31;
        int b = bid >> 5;                              // 32 blocks per batch
        int len = lengths[b];
        const float* row = u + (size_t)warp * S_;
        float sum = 0.f;
        for (int s = lane; s < len; s += 32) sum += row[s];
        #pragma unroll
        for (int o = 16; o > 0; o >>= 1) sum += __shfl_down_sync(0xffffffffu, sum, o);
        if (lane == 0) g_w[warp] = sum;
        __threadfence();
        __syncthreads();
        __shared__ int islast;
        if (tid == 0) {
            int old = atomicAdd(&g_cnt_prep[b], 1);
            islast = (old == 31);
            if (islast) g_cnt_prep[b] = 0;             // reset for next replay
        }
        __syncthreads();
        if (!islast) return;
        __threadfence();
        // ---- cvec for batch b: c[b,h] = b1[h] + sum_g w[b,g]*W1[256+g,h] ----
        __shared__ float wsh[NGF];
        if (tid < NGF) wsh[tid] = g_w[b * NGF + tid];
        __syncthreads();
        #pragma unroll
        for (int hh = 0; hh < 2; hh++) {
            int h = tid + hh * 256;
            float acc = b1[h];
            const float* Wp = W1 + (size_t)NGF * ENCH + h;
            #pragma unroll 8
            for (int g = 0; g < NGF; g++) acc = fmaf(wsh[g], Wp[(size_t)g * ENCH], acc);
            g_c[b * ENCH + h] = acc;
        }
        // ---- len==0: main never runs for this batch; emit y here ----
        if (len == 0) {
            __shared__ float redc[DECH];
            float d = fmaxf(b3[tid], 0.f);             // z = 0
            redc[tid] = d * W4[tid];
            __syncthreads();
            #pragma unroll
            for (int o = DECH / 2; o > 0; o >>= 1) {
                if (tid < o) redc[tid] += redc[tid + o];
                __syncthreads();
            }
            if (tid == 0) y[b] = redc[0] + b4[0];
        }
    } else if (bid < 2560) {
        int idx = (bid - 2048) * 256 + tid;            // 512*256
        int h = idx >> 8, g = idx & 255;
        g_w1t[h * NGF + g] = __float2half_rn(W1[(size_t)g * ENCH + h]);
    } else {
        int idx = (bid - 2560) * 256 + tid;            // 64*512
        int z = idx >> 9, h = idx & 511;
        g_w2t[z * ENCH + h] = __float2half_rn(W2[(size_t)h * ZD + z]);
    }
}

// ---------------------------------------------------------------------------
// Main HMMA kernel: per (b, 128-s tile). 256 threads = 8 warps (2m x 4n),
// warp tile m32 x n32. Pure fp16 operands, fp32 accumulate. 2 CTAs/SM.
// Last active block per batch runs the decoder inline (replaces tail kernel).
// ---------------------------------------------------------------------------
__global__ void __launch_bounds__(256, 2)
main_kernel(const float* __restrict__ u, const int* __restrict__ lengths,
            const float* __restrict__ b2, const float* __restrict__ W3,
            const float* __restrict__ b3, const float* __restrict__ W4,
            const float* __restrict__ b4, float* __restrict__ y) {
    extern __shared__ char smem[];
    u32 sb = smem_u32(smem);
    int b = blockIdx.y, tile = blockIdx.x;
    int len = lengths[b];
    int s0 = tile * TS;
    if (s0 >= len) return;

    int tid = threadIdx.x;
    int lane = tid & 31;
    int wq = tid >> 5;         // 0..7
    int wm = wq >> 2;          // 0..1  (m: 32 rows each)
    int wn = wq & 3;           // 0..3  (n: 32 s cols each)
    int gid = lane >> 2, tq = lane & 3;
    int l16 = lane & 15;
    int asel = lane >> 4;

    // ---- load u tile fp32 -> fp16, [g][s] swizzled ----
    const float* ub = u + ((size_t)b * NGF) * S_ + s0;
    #pragma unroll 4
    for (int it = 0; it < 32; it++) {
        int i = tid + 256 * it;
        int g = i >> 5, q = i & 31;
        float4 v = *(const float4*)(ub + (size_t)g * S_ + q * 4);
        u32 off = (u32)(g * 256 + (((q >> 1) ^ (g & 7)) << 4) + ((q & 1) << 3));
        *(uint2*)(smem + U_HI + off) = make_uint2(packh2(v.x, v.y), packh2(v.z, v.w));
    }
    __syncthreads();

    float zc[2][4][4];
    #pragma unroll
    for (int mt = 0; mt < 2; mt++)
        #pragma unroll
        for (int j = 0; j < 4; j++)
            #pragma unroll
            for (int r = 0; r < 4; r++) zc[mt][j][r] = 0.f;

    const float* cb = g_c + b * ENCH;

    for (int hc = 0; hc < 8; hc++) {
        // ---- load A1 slice (W1T rows hc*64..+63, all 256 g) ----
        #pragma unroll
        for (int it = 0; it < 8; it++) {
            int idx = tid + 256 * it;          // 2048 uint4
            int h = idx >> 5, c = idx & 31;
            u32 off = (u32)(h * 512 + ((c ^ (h & 7)) << 4));
            *(uint4*)(smem + A1_HI + off) =
                *(const uint4*)(g_w1t + ((size_t)(hc * 64 + h)) * NGF + c * 8);
        }
        __syncthreads();

        float hacc[2][4][4];
        #pragma unroll
        for (int mt = 0; mt < 2; mt++)
            #pragma unroll
            for (int j = 0; j < 4; j++)
                #pragma unroll
                for (int r = 0; r < 4; r++) hacc[mt][j][r] = 0.f;

        // ---- GEMM1: K = 256 (16 k16-steps), m32n32 per warp, 8 MMA/step ----
        #pragma unroll 4
        for (int k = 0; k < 16; k++) {
            u32 ah[2][4], bh[2][4];
            #pragma unroll
            for (int mt = 0; mt < 2; mt++) {
                int arow = 32 * wm + 16 * mt + l16;
                u32 ach = (u32)(((2 * k + asel) ^ (arow & 7)) << 4);
                ldsm4(ah[mt], sb + A1_HI + arow * 512 + ach);
            }
            int brow = 16 * k + l16;
            #pragma unroll
            for (int j = 0; j < 2; j++) {
                u32 bc = (u32)(((4 * wn + 2 * j + asel) ^ (brow & 7)) << 4);
                ldsm4t(bh[j], sb + U_HI + (u32)(brow * 256) + bc);
            }
            #pragma unroll
            for (int mt = 0; mt < 2; mt++)
                #pragma unroll
                for (int j = 0; j < 2; j++) {
                    mma_h(hacc[mt][2 * j],     ah[mt], bh[j][0], bh[j][1]);
                    mma_h(hacc[mt][2 * j + 1], ah[mt], bh[j][2], bh[j][3]);
                }
        }
        __syncthreads();   // all warps done reading A1 before W2 overlay

        // ---- epilogue: bias+relu, fp16, store H^T [hloc][s] ----
        #pragma unroll
        for (int mt = 0; mt < 2; mt++) {
            int hl0 = 32 * wm + 16 * mt + gid, hl1 = hl0 + 8;
            float bia0 = cb[hc * 64 + hl0], bia1 = cb[hc * 64 + hl1];
            #pragma unroll
            for (int j = 0; j < 4; j++) {
                int sbse = wn * 32 + j * 8;
                float v00 = fmaxf(hacc[mt][j][0] + bia0, 0.f);
                float v01 = fmaxf(hacc[mt][j][1] + bia0, 0.f);
                float v10 = fmaxf(hacc[mt][j][2] + bia1, 0.f);
                float v11 = fmaxf(hacc[mt][j][3] + bia1, 0.f);
                u32 off0 = (u32)(hl0 * 256 + (((sbse >> 3) ^ (hl0 & 7)) << 4) + 4 * tq);
                *(u32*)(smem + HT_HI + off0) = packh2(v00, v01);
                u32 off1 = (u32)(hl1 * 256 + (((sbse >> 3) ^ (hl1 & 7)) << 4) + 4 * tq);
                *(u32*)(smem + HT_HI + off1) = packh2(v10, v11);
            }
        }
        // ---- load W2T slice [64 z][64 h-chunk] (overlay) ----
        #pragma unroll
        for (int it = 0; it < 2; it++) {
            int idx = tid + 256 * it;          // 512 uint4
            int z = idx >> 3, c = idx & 7;
            u32 off = (u32)(z * 128 + ((c ^ (z & 7)) << 4));
            *(uint4*)(smem + W2_HI + off) =
                *(const uint4*)(g_w2t + (size_t)z * ENCH + hc * 64 + c * 8);
        }
        __syncthreads();

        // ---- GEMM2 partial: K = 64 (4 k16-steps), 8 MMA/step ----
        #pragma unroll
        for (int k2 = 0; k2 < 4; k2++) {
            u32 ah[2][4], bh[2][4];
            #pragma unroll
            for (int mt = 0; mt < 2; mt++) {
                int arow = 32 * wm + 16 * mt + l16;
                u32 ach = (u32)(((2 * k2 + asel) ^ (arow & 7)) << 4);
                ldsm4(ah[mt], sb + W2_HI + arow * 128 + ach);
            }
            int brow = 16 * k2 + l16;
            #pragma unroll
            for (int j = 0; j < 2; j++) {
                u32 bc = (u32)(((4 * wn + 2 * j + asel) ^ (brow & 7)) << 4);
                ldsm4t(bh[j], sb + HT_HI + (u32)(brow * 256) + bc);
            }
            #pragma unroll
            for (int mt = 0; mt < 2; mt++)
                #pragma unroll
                for (int j = 0; j < 2; j++) {
                    mma_h(zc[mt][2 * j],     ah[mt], bh[j][0], bh[j][1]);
                    mma_h(zc[mt][2 * j + 1], ah[mt], bh[j][2], bh[j][3]);
                }
        }
        __syncthreads();   // Ht/W2 consumed; safe to overwrite next chunk
    }

    // ---- per-tile z: bias+relu+mask, reduce over s, write g_zpart ----
    float* red = (float*)(smem + RED_O);
    #pragma unroll
    for (int mt = 0; mt < 2; mt++) {
        int z0 = 32 * wm + 16 * mt + gid, z1 = z0 + 8;
        float bz0 = b2[z0], bz1 = b2[z1];
        float p0 = 0.f, p1 = 0.f;
        #pragma unroll
        for (int j = 0; j < 4; j++) {
            int sa = s0 + wn * 32 + j * 8 + 2 * tq;
            if (sa < len) {
                p0 += fmaxf(zc[mt][j][0] + bz0, 0.f);
                p1 += fmaxf(zc[mt][j][2] + bz1, 0.f);
            }
            if (sa + 1 < len) {
                p0 += fmaxf(zc[mt][j][1] + bz0, 0.f);
                p1 += fmaxf(zc[mt][j][3] + bz1, 0.f);
            }
        }
        p0 += __shfl_xor_sync(0xffffffffu, p0, 1);
        p0 += __shfl_xor_sync(0xffffffffu, p0, 2);
        p1 += __shfl_xor_sync(0xffffffffu, p1, 1);
        p1 += __shfl_xor_sync(0xffffffffu, p1, 2);
        if (tq == 0) {
            red[wn * 64 + z0] = p0;
            red[wn * 64 + z1] = p1;
        }
    }
    __syncthreads();
    if (tid < ZD) {
        float s = 0.f;
        #pragma unroll
        for (int wnn = 0; wnn < 4; wnn++) s += red[wnn * 64 + tid];
        g_zpart[(b * NTILES + tile) * ZD + tid] = s;
    }

    // ---- last active block for this batch runs the decoder inline ----
    __threadfence();
    __syncthreads();
    __shared__ int islast;
    int nact = (len + TS - 1) / TS;
    if (tid == 0) {
        int old = atomicAdd(&g_cnt_main[b], 1);
        islast = (old == nact - 1);
        if (islast) g_cnt_main[b] = 0;                 // reset for next replay
    }
    __syncthreads();
    if (!islast) return;
    __threadfence();
    float* z_b  = (float*)(smem + HT_HI);              // HT region is dead now
    float* redc = z_b + ZD;
    if (tid < ZD) {
        float s = 0.f;
        for (int t = 0; t < nact; t++) s += g_zpart[(b * NTILES + t) * ZD + tid];
        z_b[tid] = s;
    }
    __syncthreads();
    float acc = b3[tid];
    #pragma unroll 8
    for (int k = 0; k < ZD; k++) acc = fmaf(z_b[k], W3[k * DECH + tid], acc);
    redc[tid] = fmaxf(acc, 0.f) * W4[tid];
    __syncthreads();
    #pragma unroll
    for (int o = DECH / 2; o > 0; o >>= 1) {
        if (tid < o) redc[tid] += redc[tid + o];
        __syncthreads();
    }
    if (tid == 0) y[b] = redc[0] + b4[0];
}

// ---------------------------------------------------------------------------
extern "C" void kernel_launch(void* const* d_in, const int* in_sizes, int n_in,
                              void* d_out, int out_size) {
    const float* u       = (const float*)d_in[0];
    const int*   lengths = (const int*)  d_in[1];
    const float* W1      = (const float*)d_in[2];
    const float* b1      = (const float*)d_in[3];
    const float* W2      = (const float*)d_in[4];
    const float* b2      = (const float*)d_in[5];
    const float* W3      = (const float*)d_in[6];
    const float* b3      = (const float*)d_in[7];
    const float* W4      = (const float*)d_in[8];
    const float* b4      = (const float*)d_in[9];
    float* y = (float*)d_out;

    static int smem_set = 0;
    if (!smem_set) {
        cudaFuncSetAttribute((const void*)main_kernel,
                             cudaFuncAttributeMaxDynamicSharedMemorySize, SMEM_SZ);
        smem_set = 1;
    }

    prep_all_kernel<<<2688, 256>>>(u, lengths, W1, W2, b1, b3, W4, b4, y);

    dim3 grid(NTILES, B_);
    main_kernel<<<grid, 256, SMEM_SZ>>>(u, lengths, b2, W3, b3, W4, b4, y);
}

// round 15
// speedup vs baseline: 1.1793x; 1.1793x over previous
#include <cuda_runtime.h>
#include <cuda_fp16.h>

typedef unsigned int u32;
typedef unsigned long long u64;

#define B_   64
#define NGF  256
#define S_   2048
#define ENCH 512
#define ZD   64
#define DECH 256
#define TS   128
#define NTILES 16

// ---- smem byte offsets ----
#define U_HI   0         // [256 g][128 s] fp16  64KB
#define A1_HI  65536     // [64 h][256 g] fp16   32KB
#define W2_HI  65536     // overlay on A1 (after GEMM1 done): [64 z][64 h] 8KB
#define HT_HI  98304     // [64 h][128 s] fp16   16KB
#define RED_O  114688    // 256 floats
#define SMEM_SZ 115712

__device__ float g_w[B_*NGF];
__device__ float g_c[B_*ENCH];
__device__ float g_zpart[B_*NTILES*ZD];
__device__ __half g_w1t[ENCH*NGF];   // [h][g] = fp16(W1[g][h])
__device__ __half g_w2t[ZD*ENCH];    // [z][h] = fp16(W2[h][z])
__device__ int g_cnt_prep[B_];       // zero-init; self-resetting

// ---- helpers ---------------------------------------------------------------
__device__ __forceinline__ u32 smem_u32(const void* p) {
    u32 a;
    asm("{ .reg .u64 t; cvta.to.shared.u64 t, %1; cvt.u32.u64 %0, t; }"
        : "=r"(a) : "l"(p));
    return a;
}
__device__ __forceinline__ void ldsm4(u32* r, u32 addr) {
    asm volatile("ldmatrix.sync.aligned.m8n8.x4.shared.b16 {%0,%1,%2,%3}, [%4];"
        : "=r"(r[0]), "=r"(r[1]), "=r"(r[2]), "=r"(r[3]) : "r"(addr));
}
__device__ __forceinline__ void ldsm4t(u32* r, u32 addr) {
    asm volatile("ldmatrix.sync.aligned.m8n8.x4.trans.shared.b16 {%0,%1,%2,%3}, [%4];"
        : "=r"(r[0]), "=r"(r[1]), "=r"(r[2]), "=r"(r[3]) : "r"(addr));
}
__device__ __forceinline__ void mma_h(float* c, const u32* a, u32 b0, u32 b1) {
    asm volatile("mma.sync.aligned.m16n8k16.row.col.f32.f16.f16.f32 "
        "{%0,%1,%2,%3}, {%4,%5,%6,%7}, {%8,%9}, {%0,%1,%2,%3};"
        : "+f"(c[0]), "+f"(c[1]), "+f"(c[2]), "+f"(c[3])
        : "r"(a[0]), "r"(a[1]), "r"(a[2]), "r"(a[3]), "r"(b0), "r"(b1));
}
__device__ __forceinline__ u32 packh2(float lo, float hi) {
    __half2 h = __floats2half2_rn(lo, hi);
    return *(u32*)&h;
}

// ---------------------------------------------------------------------------
// Fused prep kernel: grid sections.
//   blocks [0, 2048)    : rowsum (one warp per (b,g) row); last block per batch
//                         (32 blocks/batch) computes cvec.
//   blocks [2048, 2560) : prep_w1t
//   blocks [2560, 2688) : prep_w2t
// ---------------------------------------------------------------------------
__global__ void __launch_bounds__(256)
prep_all_kernel(const float* __restrict__ u, const int* __restrict__ lengths,
                const float* __restrict__ W1, const float* __restrict__ W2,
                const float* __restrict__ b1, const float* __restrict__ b3,
                const float* __restrict__ W4, const float* __restrict__ b4,
                float* __restrict__ y) {
    int bid = blockIdx.x;
    int tid = threadIdx.x;
    if (bid < 2048) {
        int warp = (bid * 256 + tid) >> 5;            // 0 .. 16383
        int lane = tid & 31;
        int b = bid >> 5;                              // 32 blocks per batch
        int len = lengths[b];
        const float* row = u + (size_t)warp * S_;
        float sum = 0.f;
        for (int s = lane; s < len; s += 32) sum += row[s];
        #pragma unroll
        for (int o = 16; o > 0; o >>= 1) sum += __shfl_down_sync(0xffffffffu, sum, o);
        if (lane == 0) g_w[warp] = sum;
        __threadfence();
        __syncthreads();
        __shared__ int islast;
        if (tid == 0) {
            int old = atomicAdd(&g_cnt_prep[b], 1);
            islast = (old == 31);
            if (islast) g_cnt_prep[b] = 0;             // reset for next replay
        }
        __syncthreads();
        if (!islast) return;
        __threadfence();
        // ---- cvec for batch b: c[b,h] = b1[h] + sum_g w[b,g]*W1[256+g,h] ----
        __shared__ float wsh[NGF];
        if (tid < NGF) wsh[tid] = g_w[b * NGF + tid];
        __syncthreads();
        #pragma unroll
        for (int hh = 0; hh < 2; hh++) {
            int h = tid + hh * 256;
            float acc = b1[h];
            const float* Wp = W1 + (size_t)NGF * ENCH + h;
            #pragma unroll 8
            for (int g = 0; g < NGF; g++) acc = fmaf(wsh[g], Wp[(size_t)g * ENCH], acc);
            g_c[b * ENCH + h] = acc;
        }
        // len==0 batches are handled by tail_kernel (ntiles==0 -> z=0).
    } else if (bid < 2560) {
        int idx = (bid - 2048) * 256 + tid;            // 512*256
        int h = idx >> 8, g = idx & 255;
        g_w1t[h * NGF + g] = __float2half_rn(W1[(size_t)g * ENCH + h]);
    } else {
        int idx = (bid - 2560) * 256 + tid;            // 64*512
        int z = idx >> 9, h = idx & 511;
        g_w2t[z * ENCH + h] = __float2half_rn(W2[(size_t)h * ZD + z]);
    }
}

// ---------------------------------------------------------------------------
// Main HMMA kernel: per (b, 128-s tile). 256 threads = 8 warps (2m x 4n),
// warp tile m32 x n32. Pure fp16 operands, fp32 accumulate. 2 CTAs/SM.
// ---------------------------------------------------------------------------
__global__ void __launch_bounds__(256, 2)
main_kernel(const float* __restrict__ u, const int* __restrict__ lengths,
            const float* __restrict__ b2) {
    extern __shared__ char smem[];
    u32 sb = smem_u32(smem);
    int b = blockIdx.y, tile = blockIdx.x;
    int len = lengths[b];
    int s0 = tile * TS;
    if (s0 >= len) return;

    int tid = threadIdx.x;
    int lane = tid & 31;
    int wq = tid >> 5;         // 0..7
    int wm = wq >> 2;          // 0..1  (m: 32 rows each)
    int wn = wq & 3;           // 0..3  (n: 32 s cols each)
    int gid = lane >> 2, tq = lane & 3;
    int l16 = lane & 15;
    int asel = lane >> 4;

    // ---- load u tile fp32 -> fp16, [g][s] swizzled ----
    const float* ub = u + ((size_t)b * NGF) * S_ + s0;
    #pragma unroll 4
    for (int it = 0; it < 32; it++) {
        int i = tid + 256 * it;
        int g = i >> 5, q = i & 31;
        float4 v = *(const float4*)(ub + (size_t)g * S_ + q * 4);
        u32 off = (u32)(g * 256 + (((q >> 1) ^ (g & 7)) << 4) + ((q & 1) << 3));
        *(uint2*)(smem + U_HI + off) = make_uint2(packh2(v.x, v.y), packh2(v.z, v.w));
    }
    __syncthreads();

    float zc[2][4][4];
    #pragma unroll
    for (int mt = 0; mt < 2; mt++)
        #pragma unroll
        for (int j = 0; j < 4; j++)
            #pragma unroll
            for (int r = 0; r < 4; r++) zc[mt][j][r] = 0.f;

    const float* cb = g_c + b * ENCH;

    for (int hc = 0; hc < 8; hc++) {
        // ---- load A1 slice (W1T rows hc*64..+63, all 256 g) ----
        #pragma unroll
        for (int it = 0; it < 8; it++) {
            int idx = tid + 256 * it;          // 2048 uint4
            int h = idx >> 5, c = idx & 31;
            u32 off = (u32)(h * 512 + ((c ^ (h & 7)) << 4));
            *(uint4*)(smem + A1_HI + off) =
                *(const uint4*)(g_w1t + ((size_t)(hc * 64 + h)) * NGF + c * 8);
        }
        __syncthreads();

        float hacc[2][4][4];
        #pragma unroll
        for (int mt = 0; mt < 2; mt++)
            #pragma unroll
            for (int j = 0; j < 4; j++)
                #pragma unroll
                for (int r = 0; r < 4; r++) hacc[mt][j][r] = 0.f;

        // ---- GEMM1: K = 256 (16 k16-steps), m32n32 per warp, 8 MMA/step ----
        #pragma unroll 4
        for (int k = 0; k < 16; k++) {
            u32 ah[2][4], bh[2][4];
            #pragma unroll
            for (int mt = 0; mt < 2; mt++) {
                int arow = 32 * wm + 16 * mt + l16;
                u32 ach = (u32)(((2 * k + asel) ^ (arow & 7)) << 4);
                ldsm4(ah[mt], sb + A1_HI + arow * 512 + ach);
            }
            int brow = 16 * k + l16;
            #pragma unroll
            for (int j = 0; j < 2; j++) {
                u32 bc = (u32)(((4 * wn + 2 * j + asel) ^ (brow & 7)) << 4);
                ldsm4t(bh[j], sb + U_HI + (u32)(brow * 256) + bc);
            }
            #pragma unroll
            for (int mt = 0; mt < 2; mt++)
                #pragma unroll
                for (int j = 0; j < 2; j++) {
                    mma_h(hacc[mt][2 * j],     ah[mt], bh[j][0], bh[j][1]);
                    mma_h(hacc[mt][2 * j + 1], ah[mt], bh[j][2], bh[j][3]);
                }
        }
        __syncthreads();   // all warps done reading A1 before W2 overlay

        // ---- epilogue: bias+relu, fp16, store H^T [hloc][s] ----
        #pragma unroll
        for (int mt = 0; mt < 2; mt++) {
            int hl0 = 32 * wm + 16 * mt + gid, hl1 = hl0 + 8;
            float bia0 = cb[hc * 64 + hl0], bia1 = cb[hc * 64 + hl1];
            #pragma unroll
            for (int j = 0; j < 4; j++) {
                int sbse = wn * 32 + j * 8;
                float v00 = fmaxf(hacc[mt][j][0] + bia0, 0.f);
                float v01 = fmaxf(hacc[mt][j][1] + bia0, 0.f);
                float v10 = fmaxf(hacc[mt][j][2] + bia1, 0.f);
                float v11 = fmaxf(hacc[mt][j][3] + bia1, 0.f);
                u32 off0 = (u32)(hl0 * 256 + (((sbse >> 3) ^ (hl0 & 7)) << 4) + 4 * tq);
                *(u32*)(smem + HT_HI + off0) = packh2(v00, v01);
                u32 off1 = (u32)(hl1 * 256 + (((sbse >> 3) ^ (hl1 & 7)) << 4) + 4 * tq);
                *(u32*)(smem + HT_HI + off1) = packh2(v10, v11);
            }
        }
        // ---- load W2T slice [64 z][64 h-chunk] (overlay) ----
        #pragma unroll
        for (int it = 0; it < 2; it++) {
            int idx = tid + 256 * it;          // 512 uint4
            int z = idx >> 3, c = idx & 7;
            u32 off = (u32)(z * 128 + ((c ^ (z & 7)) << 4));
            *(uint4*)(smem + W2_HI + off) =
                *(const uint4*)(g_w2t + (size_t)z * ENCH + hc * 64 + c * 8);
        }
        __syncthreads();

        // ---- GEMM2 partial: K = 64 (4 k16-steps), 8 MMA/step ----
        #pragma unroll
        for (int k2 = 0; k2 < 4; k2++) {
            u32 ah[2][4], bh[2][4];
            #pragma unroll
            for (int mt = 0; mt < 2; mt++) {
                int arow = 32 * wm + 16 * mt + l16;
                u32 ach = (u32)(((2 * k2 + asel) ^ (arow & 7)) << 4);
                ldsm4(ah[mt], sb + W2_HI + arow * 128 + ach);
            }
            int brow = 16 * k2 + l16;
            #pragma unroll
            for (int j = 0; j < 2; j++) {
                u32 bc = (u32)(((4 * wn + 2 * j + asel) ^ (brow & 7)) << 4);
                ldsm4t(bh[j], sb + HT_HI + (u32)(brow * 256) + bc);
            }
            #pragma unroll
            for (int mt = 0; mt < 2; mt++)
                #pragma unroll
                for (int j = 0; j < 2; j++) {
                    mma_h(zc[mt][2 * j],     ah[mt], bh[j][0], bh[j][1]);
                    mma_h(zc[mt][2 * j + 1], ah[mt], bh[j][2], bh[j][3]);
                }
        }
        __syncthreads();   // Ht/W2 consumed; safe to overwrite next chunk
    }

    // ---- final: bias+relu+mask, reduce over s ----
    float* red = (float*)(smem + RED_O);
    #pragma unroll
    for (int mt = 0; mt < 2; mt++) {
        int z0 = 32 * wm + 16 * mt + gid, z1 = z0 + 8;
        float bz0 = b2[z0], bz1 = b2[z1];
        float p0 = 0.f, p1 = 0.f;
        #pragma unroll
        for (int j = 0; j < 4; j++) {
            int sa = s0 + wn * 32 + j * 8 + 2 * tq;
            if (sa < len) {
                p0 += fmaxf(zc[mt][j][0] + bz0, 0.f);
                p1 += fmaxf(zc[mt][j][2] + bz1, 0.f);
            }
            if (sa + 1 < len) {
                p0 += fmaxf(zc[mt][j][1] + bz0, 0.f);
                p1 += fmaxf(zc[mt][j][3] + bz1, 0.f);
            }
        }
        p0 += __shfl_xor_sync(0xffffffffu, p0, 1);
        p0 += __shfl_xor_sync(0xffffffffu, p0, 2);
        p1 += __shfl_xor_sync(0xffffffffu, p1, 1);
        p1 += __shfl_xor_sync(0xffffffffu, p1, 2);
        if (tq == 0) {
            red[wn * 64 + z0] = p0;
            red[wn * 64 + z1] = p1;
        }
    }
    __syncthreads();
    if (tid < ZD) {
        float s = 0.f;
        #pragma unroll
        for (int wnn = 0; wnn < 4; wnn++) s += red[wnn * 64 + tid];
        g_zpart[(b * NTILES + tile) * ZD + tid] = s;
    }
}

// ---------------------------------------------------------------------------
// Tail: z = sum of partials; d = relu(z@W3+b3); y = d@W4 + b4.
// ---------------------------------------------------------------------------
__global__ void tail_kernel(const int* __restrict__ lengths,
                            const float* __restrict__ W3, const float* __restrict__ b3,
                            const float* __restrict__ W4, const float* __restrict__ b4,
                            float* __restrict__ y) {
    __shared__ float z_b[ZD];
    __shared__ float redc[DECH];
    int b = blockIdx.x;
    int tid = threadIdx.x;
    int len = lengths[b];
    int ntiles = (len + TS - 1) / TS;
    if (tid < ZD) {
        float s = 0.f;
        for (int t = 0; t < ntiles; t++) s += g_zpart[(b * NTILES + t) * ZD + tid];
        z_b[tid] = s;
    }
    __syncthreads();
    float acc = b3[tid];
    #pragma unroll 8
    for (int k = 0; k < ZD; k++) acc = fmaf(z_b[k], W3[k * DECH + tid], acc);
    redc[tid] = fmaxf(acc, 0.f) * W4[tid];
    __syncthreads();
    #pragma unroll
    for (int o = DECH / 2; o > 0; o >>= 1) {
        if (tid < o) redc[tid] += redc[tid + o];
        __syncthreads();
    }
    if (tid == 0) y[b] = redc[0] + b4[0];
}

// ---------------------------------------------------------------------------
extern "C" void kernel_launch(void* const* d_in, const int* in_sizes, int n_in,
                              void* d_out, int out_size) {
    const float* u       = (const float*)d_in[0];
    const int*   lengths = (const int*)  d_in[1];
    const float* W1      = (const float*)d_in[2];
    const float* b1      = (const float*)d_in[3];
    const float* W2      = (const float*)d_in[4];
    const float* b2      = (const float*)d_in[5];
    const float* W3      = (const float*)d_in[6];
    const float* b3      = (const float*)d_in[7];
    const float* W4      = (const float*)d_in[8];
    const float* b4      = (const float*)d_in[9];
    float* y = (float*)d_out;

    static int smem_set = 0;
    if (!smem_set) {
        cudaFuncSetAttribute((const void*)main_kernel,
                             cudaFuncAttributeMaxDynamicSharedMemorySize, SMEM_SZ);
        smem_set = 1;
    }

    prep_all_kernel<<<2688, 256>>>(u, lengths, W1, W2, b1, b3, W4, b4, y);

    dim3 grid(NTILES, B_);
    main_kernel<<<grid, 256, SMEM_SZ>>>(u, lengths, b2);

    tail_kernel<<<B_, DECH>>>(lengths, W3, b3, W4, b4, y);
}

// round 16
// speedup vs baseline: 1.2866x; 1.0910x over previous
#include <cuda_runtime.h>
#include <cuda_fp16.h>

typedef unsigned int u32;
typedef unsigned long long u64;

#define B_   64
#define NGF  256
#define S_   2048
#define ENCH 512
#define ZD   64
#define DECH 256
#define TS   128
#define NTILES 16

// ---- smem byte offsets ----
#define U_HI   0         // [256 g][128 s] fp16  64KB
#define A1_HI  65536     // [64 h][256 g] fp16   32KB
#define W2_HI  65536     // overlay on A1 (after GEMM1 done): [64 z][64 h] 8KB
#define HT_HI  98304     // [64 h][128 s] fp16   16KB
#define RED_O  114688    // 256 floats
#define SMEM_SZ 115712

__device__ float g_w[B_*NGF];
__device__ float g_c[B_*ENCH];
__device__ float g_zpart[B_*NTILES*ZD];
__device__ __half g_w1t[ENCH*NGF];   // [h][g] = fp16(W1[g][h])
__device__ __half g_w2t[ZD*ENCH];    // [z][h] = fp16(W2[h][z])

// ---- helpers ---------------------------------------------------------------
__device__ __forceinline__ u32 smem_u32(const void* p) {
    u32 a;
    asm("{ .reg .u64 t; cvta.to.shared.u64 t, %1; cvt.u32.u64 %0, t; }"
        : "=r"(a) : "l"(p));
    return a;
}
__device__ __forceinline__ void ldsm4(u32* r, u32 addr) {
    asm volatile("ldmatrix.sync.aligned.m8n8.x4.shared.b16 {%0,%1,%2,%3}, [%4];"
        : "=r"(r[0]), "=r"(r[1]), "=r"(r[2]), "=r"(r[3]) : "r"(addr));
}
__device__ __forceinline__ void ldsm4t(u32* r, u32 addr) {
    asm volatile("ldmatrix.sync.aligned.m8n8.x4.trans.shared.b16 {%0,%1,%2,%3}, [%4];"
        : "=r"(r[0]), "=r"(r[1]), "=r"(r[2]), "=r"(r[3]) : "r"(addr));
}
__device__ __forceinline__ void mma_h(float* c, const u32* a, u32 b0, u32 b1) {
    asm volatile("mma.sync.aligned.m16n8k16.row.col.f32.f16.f16.f32 "
        "{%0,%1,%2,%3}, {%4,%5,%6,%7}, {%8,%9}, {%0,%1,%2,%3};"
        : "+f"(c[0]), "+f"(c[1]), "+f"(c[2]), "+f"(c[3])
        : "r"(a[0]), "r"(a[1]), "r"(a[2]), "r"(a[3]), "r"(b0), "r"(b1));
}
__device__ __forceinline__ u32 packh2(float lo, float hi) {
    __half2 h = __floats2half2_rn(lo, hi);
    return *(u32*)&h;
}

// ---------------------------------------------------------------------------
// Fused prep kernel (no cross-block sync): grid sections.
//   blocks [0, 2048)    : rowsum, float4-vectorized (one warp per (b,g) row)
//   blocks [2048, 2560) : prep_w1t
//   blocks [2560, 2688) : prep_w2t
// ---------------------------------------------------------------------------
__global__ void __launch_bounds__(256)
prep_all_kernel(const float* __restrict__ u, const int* __restrict__ lengths,
                const float* __restrict__ W1, const float* __restrict__ W2) {
    int bid = blockIdx.x;
    int tid = threadIdx.x;
    if (bid < 2048) {
        int warp = (bid * 256 + tid) >> 5;            // 0 .. 16383
        int lane = tid & 31;
        int b = warp >> 8;
        int len = lengths[b];
        const float*  row  = u + (size_t)warp * S_;
        const float4* row4 = (const float4*)row;
        int n4 = len >> 2;
        float sum = 0.f;
        for (int i = lane; i < n4; i += 32) {
            float4 v = row4[i];
            sum += (v.x + v.y) + (v.z + v.w);
        }
        if (lane < (len & 3)) sum += row[n4 * 4 + lane];
        #pragma unroll
        for (int o = 16; o > 0; o >>= 1) sum += __shfl_down_sync(0xffffffffu, sum, o);
        if (lane == 0) g_w[warp] = sum;
    } else if (bid < 2560) {
        int idx = (bid - 2048) * 256 + tid;            // 512*256
        int h = idx >> 8, g = idx & 255;
        g_w1t[h * NGF + g] = __float2half_rn(W1[(size_t)g * ENCH + h]);
    } else {
        int idx = (bid - 2560) * 256 + tid;            // 64*512
        int z = idx >> 9, h = idx & 511;
        g_w2t[z * ENCH + h] = __float2half_rn(W2[(size_t)h * ZD + z]);
    }
}

// ---------------------------------------------------------------------------
// cvec: c[b,h] = b1[h] + sum_g w[b,g] * W1[256+g, h]
// ---------------------------------------------------------------------------
__global__ void cvec_kernel(const float* __restrict__ W1,
                            const float* __restrict__ b1) {
    __shared__ float wsh[NGF];
    int b = blockIdx.x;
    int h = threadIdx.x;          // 512 threads
    if (h < NGF) wsh[h] = g_w[b * NGF + h];
    __syncthreads();
    float acc = b1[h];
    const float* Wp = W1 + (size_t)NGF * ENCH + h;
    #pragma unroll 8
    for (int g = 0; g < NGF; g++) acc = fmaf(wsh[g], Wp[(size_t)g * ENCH], acc);
    g_c[b * ENCH + h] = acc;
}

// ---------------------------------------------------------------------------
// Main HMMA kernel: per (b, 128-s tile). 256 threads = 8 warps (2m x 4n),
// warp tile m32 x n32. Pure fp16 operands, fp32 accumulate. 2 CTAs/SM.
// ---------------------------------------------------------------------------
__global__ void __launch_bounds__(256, 2)
main_kernel(const float* __restrict__ u, const int* __restrict__ lengths,
            const float* __restrict__ b2) {
    extern __shared__ char smem[];
    u32 sb = smem_u32(smem);
    int b = blockIdx.y, tile = blockIdx.x;
    int len = lengths[b];
    int s0 = tile * TS;
    if (s0 >= len) return;

    int tid = threadIdx.x;
    int lane = tid & 31;
    int wq = tid >> 5;         // 0..7
    int wm = wq >> 2;          // 0..1  (m: 32 rows each)
    int wn = wq & 3;           // 0..3  (n: 32 s cols each)
    int gid = lane >> 2, tq = lane & 3;
    int l16 = lane & 15;
    int asel = lane >> 4;

    // ---- load u tile fp32 -> fp16, [g][s] swizzled ----
    const float* ub = u + ((size_t)b * NGF) * S_ + s0;
    #pragma unroll 4
    for (int it = 0; it < 32; it++) {
        int i = tid + 256 * it;
        int g = i >> 5, q = i & 31;
        float4 v = *(const float4*)(ub + (size_t)g * S_ + q * 4);
        u32 off = (u32)(g * 256 + (((q >> 1) ^ (g & 7)) << 4) + ((q & 1) << 3));
        *(uint2*)(smem + U_HI + off) = make_uint2(packh2(v.x, v.y), packh2(v.z, v.w));
    }
    __syncthreads();

    float zc[2][4][4];
    #pragma unroll
    for (int mt = 0; mt < 2; mt++)
        #pragma unroll
        for (int j = 0; j < 4; j++)
            #pragma unroll
            for (int r = 0; r < 4; r++) zc[mt][j][r] = 0.f;

    const float* cb = g_c + b * ENCH;

    for (int hc = 0; hc < 8; hc++) {
        // ---- load A1 slice (W1T rows hc*64..+63, all 256 g) ----
        #pragma unroll
        for (int it = 0; it < 8; it++) {
            int idx = tid + 256 * it;          // 2048 uint4
            int h = idx >> 5, c = idx & 31;
            u32 off = (u32)(h * 512 + ((c ^ (h & 7)) << 4));
            *(uint4*)(smem + A1_HI + off) =
                *(const uint4*)(g_w1t + ((size_t)(hc * 64 + h)) * NGF + c * 8);
        }
        __syncthreads();

        float hacc[2][4][4];
        #pragma unroll
        for (int mt = 0; mt < 2; mt++)
            #pragma unroll
            for (int j = 0; j < 4; j++)
                #pragma unroll
                for (int r = 0; r < 4; r++) hacc[mt][j][r] = 0.f;

        // ---- GEMM1: K = 256 (16 k16-steps), m32n32 per warp, 8 MMA/step ----
        #pragma unroll 4
        for (int k = 0; k < 16; k++) {
            u32 ah[2][4], bh[2][4];
            #pragma unroll
            for (int mt = 0; mt < 2; mt++) {
                int arow = 32 * wm + 16 * mt + l16;
                u32 ach = (u32)(((2 * k + asel) ^ (arow & 7)) << 4);
                ldsm4(ah[mt], sb + A1_HI + arow * 512 + ach);
            }
            int brow = 16 * k + l16;
            #pragma unroll
            for (int j = 0; j < 2; j++) {
                u32 bc = (u32)(((4 * wn + 2 * j + asel) ^ (brow & 7)) << 4);
                ldsm4t(bh[j], sb + U_HI + (u32)(brow * 256) + bc);
            }
            #pragma unroll
            for (int mt = 0; mt < 2; mt++)
                #pragma unroll
                for (int j = 0; j < 2; j++) {
                    mma_h(hacc[mt][2 * j],     ah[mt], bh[j][0], bh[j][1]);
                    mma_h(hacc[mt][2 * j + 1], ah[mt], bh[j][2], bh[j][3]);
                }
        }
        __syncthreads();   // all warps done reading A1 before W2 overlay

        // ---- epilogue: bias+relu, fp16, store H^T [hloc][s] ----
        #pragma unroll
        for (int mt = 0; mt < 2; mt++) {
            int hl0 = 32 * wm + 16 * mt + gid, hl1 = hl0 + 8;
            float bia0 = cb[hc * 64 + hl0], bia1 = cb[hc * 64 + hl1];
            #pragma unroll
            for (int j = 0; j < 4; j++) {
                int sbse = wn * 32 + j * 8;
                float v00 = fmaxf(hacc[mt][j][0] + bia0, 0.f);
                float v01 = fmaxf(hacc[mt][j][1] + bia0, 0.f);
                float v10 = fmaxf(hacc[mt][j][2] + bia1, 0.f);
                float v11 = fmaxf(hacc[mt][j][3] + bia1, 0.f);
                u32 off0 = (u32)(hl0 * 256 + (((sbse >> 3) ^ (hl0 & 7)) << 4) + 4 * tq);
                *(u32*)(smem + HT_HI + off0) = packh2(v00, v01);
                u32 off1 = (u32)(hl1 * 256 + (((sbse >> 3) ^ (hl1 & 7)) << 4) + 4 * tq);
                *(u32*)(smem + HT_HI + off1) = packh2(v10, v11);
            }
        }
        // ---- load W2T slice [64 z][64 h-chunk] (overlay) ----
        #pragma unroll
        for (int it = 0; it < 2; it++) {
            int idx = tid + 256 * it;          // 512 uint4
            int z = idx >> 3, c = idx & 7;
            u32 off = (u32)(z * 128 + ((c ^ (z & 7)) << 4));
            *(uint4*)(smem + W2_HI + off) =
                *(const uint4*)(g_w2t + (size_t)z * ENCH + hc * 64 + c * 8);
        }
        __syncthreads();

        // ---- GEMM2 partial: K = 64 (4 k16-steps), 8 MMA/step ----
        #pragma unroll
        for (int k2 = 0; k2 < 4; k2++) {
            u32 ah[2][4], bh[2][4];
            #pragma unroll
            for (int mt = 0; mt < 2; mt++) {
                int arow = 32 * wm + 16 * mt + l16;
                u32 ach = (u32)(((2 * k2 + asel) ^ (arow & 7)) << 4);
                ldsm4(ah[mt], sb + W2_HI + arow * 128 + ach);
            }
            int brow = 16 * k2 + l16;
            #pragma unroll
            for (int j = 0; j < 2; j++) {
                u32 bc = (u32)(((4 * wn + 2 * j + asel) ^ (brow & 7)) << 4);
                ldsm4t(bh[j], sb + HT_HI + (u32)(brow * 256) + bc);
            }
            #pragma unroll
            for (int mt = 0; mt < 2; mt++)
                #pragma unroll
                for (int j = 0; j < 2; j++) {
                    mma_h(zc[mt][2 * j],     ah[mt], bh[j][0], bh[j][1]);
                    mma_h(zc[mt][2 * j + 1], ah[mt], bh[j][2], bh[j][3]);
                }
        }
        __syncthreads();   // Ht/W2 consumed; safe to overwrite next chunk
    }

    // ---- final: bias+relu+mask, reduce over s ----
    float* red = (float*)(smem + RED_O);
    #pragma unroll
    for (int mt = 0; mt < 2; mt++) {
        int z0 = 32 * wm + 16 * mt + gid, z1 = z0 + 8;
        float bz0 = b2[z0], bz1 = b2[z1];
        float p0 = 0.f, p1 = 0.f;
        #pragma unroll
        for (int j = 0; j < 4; j++) {
            int sa = s0 + wn * 32 + j * 8 + 2 * tq;
            if (sa < len) {
                p0 += fmaxf(zc[mt][j][0] + bz0, 0.f);
                p1 += fmaxf(zc[mt][j][2] + bz1, 0.f);
            }
            if (sa + 1 < len) {
                p0 += fmaxf(zc[mt][j][1] + bz0, 0.f);
                p1 += fmaxf(zc[mt][j][3] + bz1, 0.f);
            }
        }
        p0 += __shfl_xor_sync(0xffffffffu, p0, 1);
        p0 += __shfl_xor_sync(0xffffffffu, p0, 2);
        p1 += __shfl_xor_sync(0xffffffffu, p1, 1);
        p1 += __shfl_xor_sync(0xffffffffu, p1, 2);
        if (tq == 0) {
            red[wn * 64 + z0] = p0;
            red[wn * 64 + z1] = p1;
        }
    }
    __syncthreads();
    if (tid < ZD) {
        float s = 0.f;
        #pragma unroll
        for (int wnn = 0; wnn < 4; wnn++) s += red[wnn * 64 + tid];
        g_zpart[(b * NTILES + tile) * ZD + tid] = s;
    }
}

// ---------------------------------------------------------------------------
// Tail: z = sum of partials; d = relu(z@W3+b3); y = d@W4 + b4.
// ---------------------------------------------------------------------------
__global__ void tail_kernel(const int* __restrict__ lengths,
                            const float* __restrict__ W3, const float* __restrict__ b3,
                            const float* __restrict__ W4, const float* __restrict__ b4,
                            float* __restrict__ y) {
    __shared__ float z_b[ZD];
    __shared__ float redc[DECH];
    int b = blockIdx.x;
    int tid = threadIdx.x;
    int len = lengths[b];
    int ntiles = (len + TS - 1) / TS;
    if (tid < ZD) {
        float s = 0.f;
        for (int t = 0; t < ntiles; t++) s += g_zpart[(b * NTILES + t) * ZD + tid];
        z_b[tid] = s;
    }
    __syncthreads();
    float acc = b3[tid];
    #pragma unroll 8
    for (int k = 0; k < ZD; k++) acc = fmaf(z_b[k], W3[k * DECH + tid], acc);
    redc[tid] = fmaxf(acc, 0.f) * W4[tid];
    __syncthreads();
    #pragma unroll
    for (int o = DECH / 2; o > 0; o >>= 1) {
        if (tid < o) redc[tid] += redc[tid + o];
        __syncthreads();
    }
    if (tid == 0) y[b] = redc[0] + b4[0];
}

// ---------------------------------------------------------------------------
extern "C" void kernel_launch(void* const* d_in, const int* in_sizes, int n_in,
                              void* d_out, int out_size) {
    const float* u       = (const float*)d_in[0];
    const int*   lengths = (const int*)  d_in[1];
    const float* W1      = (const float*)d_in[2];
    const float* b1      = (const float*)d_in[3];
    const float* W2      = (const float*)d_in[4];
    const float* b2      = (const float*)d_in[5];
    const float* W3      = (const float*)d_in[6];
    const float* b3      = (const float*)d_in[7];
    const float* W4      = (const float*)d_in[8];
    const float* b4      = (const float*)d_in[9];
    float* y = (float*)d_out;

    static int smem_set = 0;
    if (!smem_set) {
        cudaFuncSetAttribute((const void*)main_kernel,
                             cudaFuncAttributeMaxDynamicSharedMemorySize, SMEM_SZ);
        smem_set = 1;
    }

    prep_all_kernel<<<2688, 256>>>(u, lengths, W1, W2);
    cvec_kernel<<<B_, ENCH>>>(W1, b1);

    dim3 grid(NTILES, B_);
    main_kernel<<<grid, 256, SMEM_SZ>>>(u, lengths, b2);

    tail_kernel<<<B_, DECH>>>(lengths, W3, b3, W4, b4, y);
}

// round 17
// speedup vs baseline: 1.3096x; 1.0179x over previous
#include <cuda_runtime.h>
#include <cuda_fp16.h>

typedef unsigned int u32;
typedef unsigned long long u64;

#define B_   64
#define NGF  256
#define S_   2048
#define ENCH 512
#define ZD   64
#define DECH 256
#define TS   128
#define NTILES 16

// ---- smem byte offsets (main kernel) ----
#define U_HI   0         // [256 g][128 s] fp16  64KB
#define A1_HI  65536     // [64 h][256 g] fp16   32KB
#define W2_HI  65536     // overlay on A1 (after GEMM1 done): [64 z][64 h] 8KB
#define HT_HI  98304     // [64 h][128 s] fp16   16KB
#define RED_O  114688    // 256 floats
#define SMEM_SZ 115712

__device__ float g_w[B_*NGF];
__device__ float g_c[B_*ENCH];
__device__ float g_zpart[B_*NTILES*ZD];
__device__ __half g_w1t[ENCH*NGF];   // [h][g] = fp16(W1[g][h])
__device__ __half g_w2t[ZD*ENCH];    // [z][h] = fp16(W2[h][z])

// ---- helpers ---------------------------------------------------------------
__device__ __forceinline__ u32 smem_u32(const void* p) {
    u32 a;
    asm("{ .reg .u64 t; cvta.to.shared.u64 t, %1; cvt.u32.u64 %0, t; }"
        : "=r"(a) : "l"(p));
    return a;
}
__device__ __forceinline__ void ldsm4(u32* r, u32 addr) {
    asm volatile("ldmatrix.sync.aligned.m8n8.x4.shared.b16 {%0,%1,%2,%3}, [%4];"
        : "=r"(r[0]), "=r"(r[1]), "=r"(r[2]), "=r"(r[3]) : "r"(addr));
}
__device__ __forceinline__ void ldsm4t(u32* r, u32 addr) {
    asm volatile("ldmatrix.sync.aligned.m8n8.x4.trans.shared.b16 {%0,%1,%2,%3}, [%4];"
        : "=r"(r[0]), "=r"(r[1]), "=r"(r[2]), "=r"(r[3]) : "r"(addr));
}
__device__ __forceinline__ void mma_h(float* c, const u32* a, u32 b0, u32 b1) {
    asm volatile("mma.sync.aligned.m16n8k16.row.col.f32.f16.f16.f32 "
        "{%0,%1,%2,%3}, {%4,%5,%6,%7}, {%8,%9}, {%0,%1,%2,%3};"
        : "+f"(c[0]), "+f"(c[1]), "+f"(c[2]), "+f"(c[3])
        : "r"(a[0]), "r"(a[1]), "r"(a[2]), "r"(a[3]), "r"(b0), "r"(b1));
}
__device__ __forceinline__ u32 packh2(float lo, float hi) {
    __half2 h = __floats2half2_rn(lo, hi);
    return *(u32*)&h;
}

// ---------------------------------------------------------------------------
// Fused prep kernel: grid sections.
//   blocks [0, 2048)      : rowsum, float4-vectorized (one warp per row)
//   blocks [2048, 2080)   : w1t tiled transpose (64x64 tiles via smem)
//   blocks [2080, 2088)   : w2t tiled transpose
// ---------------------------------------------------------------------------
__global__ void __launch_bounds__(256)
prep_all_kernel(const float* __restrict__ u, const int* __restrict__ lengths,
                const float* __restrict__ W1, const float* __restrict__ W2) {
    __shared__ __half sm[64][65];
    int bid = blockIdx.x;
    int tid = threadIdx.x;
    if (bid < 2048) {
        int warp = (bid * 256 + tid) >> 5;            // 0 .. 16383
        int lane = tid & 31;
        int b = warp >> 8;
        int len = lengths[b];
        const float*  row  = u + (size_t)warp * S_;
        const float4* row4 = (const float4*)row;
        int n4 = len >> 2;
        float sum = 0.f;
        #pragma unroll 4
        for (int i = lane; i < n4; i += 32) {
            float4 v = row4[i];
            sum += (v.x + v.y) + (v.z + v.w);
        }
        if (lane < (len & 3)) sum += row[n4 * 4 + lane];
        #pragma unroll
        for (int o = 16; o > 0; o >>= 1) sum += __shfl_down_sync(0xffffffffu, sum, o);
        if (lane == 0) g_w[warp] = sum;
    } else if (bid < 2080) {
        // w1t[h][g] = fp16(W1[g][h]): 64x64 tile, coalesced both sides
        int t = bid - 2048;                            // 0..31
        int g0 = (t & 3) * 64, h0 = (t >> 2) * 64;
        #pragma unroll
        for (int it = 0; it < 16; it++) {
            int idx = tid + 256 * it;
            int i = idx >> 6, j = idx & 63;            // i: g-row, j: h-col
            sm[i][j] = __float2half_rn(W1[(size_t)(g0 + i) * ENCH + h0 + j]);
        }
        __syncthreads();
        #pragma unroll
        for (int it = 0; it < 16; it++) {
            int idx = tid + 256 * it;
            int i2 = idx & 63, j2 = idx >> 6;          // write coalesced along g
            g_w1t[(size_t)(h0 + j2) * NGF + g0 + i2] = sm[i2][j2];
        }
    } else {
        // w2t[z][h] = fp16(W2[h][z]): 64h x 64z tile
        int t = bid - 2080;                            // 0..7
        int h0 = t * 64;
        #pragma unroll
        for (int it = 0; it < 16; it++) {
            int idx = tid + 256 * it;
            int i = idx >> 6, z = idx & 63;            // i: h-row, z: z-col
            sm[i][z] = __float2half_rn(W2[(size_t)(h0 + i) * ZD + z]);
        }
        __syncthreads();
        #pragma unroll
        for (int it = 0; it < 16; it++) {
            int idx = tid + 256 * it;
            int i2 = idx & 63, z = idx >> 6;           // write coalesced along h
            g_w2t[(size_t)z * ENCH + h0 + i2] = sm[i2][z];
        }
    }
}

// ---------------------------------------------------------------------------
// cvec: c[b,h] = b1[h] + sum_g w[b,g] * W1[256+g, h]
// ---------------------------------------------------------------------------
__global__ void cvec_kernel(const float* __restrict__ W1,
                            const float* __restrict__ b1) {
    __shared__ float wsh[NGF];
    int b = blockIdx.x;
    int h = threadIdx.x;          // 512 threads
    if (h < NGF) wsh[h] = g_w[b * NGF + h];
    __syncthreads();
    float acc = b1[h];
    const float* Wp = W1 + (size_t)NGF * ENCH + h;
    #pragma unroll 8
    for (int g = 0; g < NGF; g++) acc = fmaf(wsh[g], Wp[(size_t)g * ENCH], acc);
    g_c[b * ENCH + h] = acc;
}

// ---------------------------------------------------------------------------
// Main HMMA kernel: per (b, 128-s tile). 256 threads = 8 warps (2m x 4n),
// warp tile m32 x n32. Pure fp16 operands, fp32 accumulate. 2 CTAs/SM.
// ---------------------------------------------------------------------------
__global__ void __launch_bounds__(256, 2)
main_kernel(const float* __restrict__ u, const int* __restrict__ lengths,
            const float* __restrict__ b2) {
    extern __shared__ char smem[];
    u32 sb = smem_u32(smem);
    int b = blockIdx.y, tile = blockIdx.x;
    int len = lengths[b];
    int s0 = tile * TS;
    if (s0 >= len) return;

    int tid = threadIdx.x;
    int lane = tid & 31;
    int wq = tid >> 5;         // 0..7
    int wm = wq >> 2;          // 0..1  (m: 32 rows each)
    int wn = wq & 3;           // 0..3  (n: 32 s cols each)
    int gid = lane >> 2, tq = lane & 3;
    int l16 = lane & 15;
    int asel = lane >> 4;

    // ---- load u tile fp32 -> fp16, [g][s] swizzled ----
    const float* ub = u + ((size_t)b * NGF) * S_ + s0;
    #pragma unroll 4
    for (int it = 0; it < 32; it++) {
        int i = tid + 256 * it;
        int g = i >> 5, q = i & 31;
        float4 v = *(const float4*)(ub + (size_t)g * S_ + q * 4);
        u32 off = (u32)(g * 256 + (((q >> 1) ^ (g & 7)) << 4) + ((q & 1) << 3));
        *(uint2*)(smem + U_HI + off) = make_uint2(packh2(v.x, v.y), packh2(v.z, v.w));
    }
    __syncthreads();

    float zc[2][4][4];
    #pragma unroll
    for (int mt = 0; mt < 2; mt++)
        #pragma unroll
        for (int j = 0; j < 4; j++)
            #pragma unroll
            for (int r = 0; r < 4; r++) zc[mt][j][r] = 0.f;

    const float* cb = g_c + b * ENCH;

    for (int hc = 0; hc < 8; hc++) {
        // ---- load A1 slice (W1T rows hc*64..+63, all 256 g) ----
        #pragma unroll
        for (int it = 0; it < 8; it++) {
            int idx = tid + 256 * it;          // 2048 uint4
            int h = idx >> 5, c = idx & 31;
            u32 off = (u32)(h * 512 + ((c ^ (h & 7)) << 4));
            *(uint4*)(smem + A1_HI + off) =
                *(const uint4*)(g_w1t + ((size_t)(hc * 64 + h)) * NGF + c * 8);
        }
        __syncthreads();

        float hacc[2][4][4];
        #pragma unroll
        for (int mt = 0; mt < 2; mt++)
            #pragma unroll
            for (int j = 0; j < 4; j++)
                #pragma unroll
                for (int r = 0; r < 4; r++) hacc[mt][j][r] = 0.f;

        // ---- GEMM1: K = 256 (16 k16-steps), m32n32 per warp, 8 MMA/step ----
        #pragma unroll 4
        for (int k = 0; k < 16; k++) {
            u32 ah[2][4], bh[2][4];
            #pragma unroll
            for (int mt = 0; mt < 2; mt++) {
                int arow = 32 * wm + 16 * mt + l16;
                u32 ach = (u32)(((2 * k + asel) ^ (arow & 7)) << 4);
                ldsm4(ah[mt], sb + A1_HI + arow * 512 + ach);
            }
            int brow = 16 * k + l16;
            #pragma unroll
            for (int j = 0; j < 2; j++) {
                u32 bc = (u32)(((4 * wn + 2 * j + asel) ^ (brow & 7)) << 4);
                ldsm4t(bh[j], sb + U_HI + (u32)(brow * 256) + bc);
            }
            #pragma unroll
            for (int mt = 0; mt < 2; mt++)
                #pragma unroll
                for (int j = 0; j < 2; j++) {
                    mma_h(hacc[mt][2 * j],     ah[mt], bh[j][0], bh[j][1]);
                    mma_h(hacc[mt][2 * j + 1], ah[mt], bh[j][2], bh[j][3]);
                }
        }
        __syncthreads();   // all warps done reading A1 before W2 overlay

        // ---- epilogue: bias+relu, fp16, store H^T [hloc][s] ----
        #pragma unroll
        for (int mt = 0; mt < 2; mt++) {
            int hl0 = 32 * wm + 16 * mt + gid, hl1 = hl0 + 8;
            float bia0 = cb[hc * 64 + hl0], bia1 = cb[hc * 64 + hl1];
            #pragma unroll
            for (int j = 0; j < 4; j++) {
                int sbse = wn * 32 + j * 8;
                float v00 = fmaxf(hacc[mt][j][0] + bia0, 0.f);
                float v01 = fmaxf(hacc[mt][j][1] + bia0, 0.f);
                float v10 = fmaxf(hacc[mt][j][2] + bia1, 0.f);
                float v11 = fmaxf(hacc[mt][j][3] + bia1, 0.f);
                u32 off0 = (u32)(hl0 * 256 + (((sbse >> 3) ^ (hl0 & 7)) << 4) + 4 * tq);
                *(u32*)(smem + HT_HI + off0) = packh2(v00, v01);
                u32 off1 = (u32)(hl1 * 256 + (((sbse >> 3) ^ (hl1 & 7)) << 4) + 4 * tq);
                *(u32*)(smem + HT_HI + off1) = packh2(v10, v11);
            }
        }
        // ---- load W2T slice [64 z][64 h-chunk] (overlay) ----
        #pragma unroll
        for (int it = 0; it < 2; it++) {
            int idx = tid + 256 * it;          // 512 uint4
            int z = idx >> 3, c = idx & 7;
            u32 off = (u32)(z * 128 + ((c ^ (z & 7)) << 4));
            *(uint4*)(smem + W2_HI + off) =
                *(const uint4*)(g_w2t + (size_t)z * ENCH + hc * 64 + c * 8);
        }
        __syncthreads();

        // ---- GEMM2 partial: K = 64 (4 k16-steps), 8 MMA/step ----
        #pragma unroll
        for (int k2 = 0; k2 < 4; k2++) {
            u32 ah[2][4], bh[2][4];
            #pragma unroll
            for (int mt = 0; mt < 2; mt++) {
                int arow = 32 * wm + 16 * mt + l16;
                u32 ach = (u32)(((2 * k2 + asel) ^ (arow & 7)) << 4);
                ldsm4(ah[mt], sb + W2_HI + arow * 128 + ach);
            }
            int brow = 16 * k2 + l16;
            #pragma unroll
            for (int j = 0; j < 2; j++) {
                u32 bc = (u32)(((4 * wn + 2 * j + asel) ^ (brow & 7)) << 4);
                ldsm4t(bh[j], sb + HT_HI + (u32)(brow * 256) + bc);
            }
            #pragma unroll
            for (int mt = 0; mt < 2; mt++)
                #pragma unroll
                for (int j = 0; j < 2; j++) {
                    mma_h(zc[mt][2 * j],     ah[mt], bh[j][0], bh[j][1]);
                    mma_h(zc[mt][2 * j + 1], ah[mt], bh[j][2], bh[j][3]);
                }
        }
        __syncthreads();   // Ht/W2 consumed; safe to overwrite next chunk
    }

    // ---- final: bias+relu+mask, reduce over s ----
    float* red = (float*)(smem + RED_O);
    #pragma unroll
    for (int mt = 0; mt < 2; mt++) {
        int z0 = 32 * wm + 16 * mt + gid, z1 = z0 + 8;
        float bz0 = b2[z0], bz1 = b2[z1];
        float p0 = 0.f, p1 = 0.f;
        #pragma unroll
        for (int j = 0; j < 4; j++) {
            int sa = s0 + wn * 32 + j * 8 + 2 * tq;
            if (sa < len) {
                p0 += fmaxf(zc[mt][j][0] + bz0, 0.f);
                p1 += fmaxf(zc[mt][j][2] + bz1, 0.f);
            }
            if (sa + 1 < len) {
                p0 += fmaxf(zc[mt][j][1] + bz0, 0.f);
                p1 += fmaxf(zc[mt][j][3] + bz1, 0.f);
            }
        }
        p0 += __shfl_xor_sync(0xffffffffu, p0, 1);
        p0 += __shfl_xor_sync(0xffffffffu, p0, 2);
        p1 += __shfl_xor_sync(0xffffffffu, p1, 1);
        p1 += __shfl_xor_sync(0xffffffffu, p1, 2);
        if (tq == 0) {
            red[wn * 64 + z0] = p0;
            red[wn * 64 + z1] = p1;
        }
    }
    __syncthreads();
    if (tid < ZD) {
        float s = 0.f;
        #pragma unroll
        for (int wnn = 0; wnn < 4; wnn++) s += red[wnn * 64 + tid];
        g_zpart[(b * NTILES + tile) * ZD + tid] = s;
    }
}

// ---------------------------------------------------------------------------
// Tail: z = sum of partials; d = relu(z@W3+b3); y = d@W4 + b4.
// ---------------------------------------------------------------------------
__global__ void tail_kernel(const int* __restrict__ lengths,
                            const float* __restrict__ W3, const float* __restrict__ b3,
                            const float* __restrict__ W4, const float* __restrict__ b4,
                            float* __restrict__ y) {
    __shared__ float z_b[ZD];
    __shared__ float redc[DECH];
    int b = blockIdx.x;
    int tid = threadIdx.x;
    int len = lengths[b];
    int ntiles = (len + TS - 1) / TS;
    if (tid < ZD) {
        float s = 0.f;
        for (int t = 0; t < ntiles; t++) s += g_zpart[(b * NTILES + t) * ZD + tid];
        z_b[tid] = s;
    }
    __syncthreads();
    float a0 = b3[tid], a1 = 0.f;
    #pragma unroll 16
    for (int k = 0; k < ZD; k += 2) {
        a0 = fmaf(z_b[k],     W3[k * DECH + tid],       a0);
        a1 = fmaf(z_b[k + 1], W3[(k + 1) * DECH + tid], a1);
    }
    redc[tid] = fmaxf(a0 + a1, 0.f) * W4[tid];
    __syncthreads();
    #pragma unroll
    for (int o = DECH / 2; o > 0; o >>= 1) {
        if (tid < o) redc[tid] += redc[tid + o];
        __syncthreads();
    }
    if (tid == 0) y[b] = redc[0] + b4[0];
}

// ---------------------------------------------------------------------------
extern "C" void kernel_launch(void* const* d_in, const int* in_sizes, int n_in,
                              void* d_out, int out_size) {
    const float* u       = (const float*)d_in[0];
    const int*   lengths = (const int*)  d_in[1];
    const float* W1      = (const float*)d_in[2];
    const float* b1      = (const float*)d_in[3];
    const float* W2      = (const float*)d_in[4];
    const float* b2      = (const float*)d_in[5];
    const float* W3      = (const float*)d_in[6];
    const float* b3      = (const float*)d_in[7];
    const float* W4      = (const float*)d_in[8];
    const float* b4      = (const float*)d_in[9];
    float* y = (float*)d_out;

    static int smem_set = 0;
    if (!smem_set) {
        cudaFuncSetAttribute((const void*)main_kernel,
                             cudaFuncAttributeMaxDynamicSharedMemorySize, SMEM_SZ);
        smem_set = 1;
    }

    prep_all_kernel<<<2088, 256>>>(u, lengths, W1, W2);
    cvec_kernel<<<B_, ENCH>>>(W1, b1);

    dim3 grid(NTILES, B_);
    main_kernel<<<grid, 256, SMEM_SZ>>>(u, lengths, b2);

    tail_kernel<<<B_, DECH>>>(lengths, W3, b3, W4, b4, y);
}